// round 1
// baseline (speedup 1.0000x reference)
#include <cuda_runtime.h>
#include <cuda_bf16.h>

#define B_ 8
#define T_ 2048
#define C_ 1024
#define H_ 64
#define M_TOTAL (B_ * T_)   // 16384 rows

// Scratch for q, k, v projections (allocation-free rule: __device__ globals)
__device__ float g_q[M_TOTAL * H_];
__device__ float g_k[M_TOTAL * H_];
__device__ float g_v[M_TOTAL * H_];

// ---------------------------------------------------------------------------
// Kernel 1: fused QKV projection.
// out[q|k|v] (16384 x 64) = x (16384 x 1024) @ W (1024 x 64), three weights
// fused as a single BN=192 GEMM so x is read once.
// Tiling: BM=64, BN=192, BK=16, 256 threads, thread tile 4x12.
// ---------------------------------------------------------------------------
#define QKV_BM 64
#define QKV_BK 16
#define QKV_BN 192

__global__ __launch_bounds__(256) void qkv_kernel(
    const float* __restrict__ x,
    const float* __restrict__ Wq,
    const float* __restrict__ Wk,
    const float* __restrict__ Wv) {
  __shared__ float As[QKV_BK][68];        // [k][m], padded to 68
  __shared__ float Bs[QKV_BK][QKV_BN];    // [k][n]

  const int t = threadIdx.x;
  const int tx = t & 15;        // 16 col groups (12 cols each)
  const int ty = t >> 4;        // 16 row groups (4 rows each)
  const int row0 = blockIdx.x * QKV_BM;
  const int lrow = t >> 2;      // x-tile row this thread loads
  const int lseg = t & 3;       // which 4-float segment of BK

  float acc[4][12];
#pragma unroll
  for (int i = 0; i < 4; i++)
#pragma unroll
    for (int j = 0; j < 12; j++) acc[i][j] = 0.f;

  for (int k0 = 0; k0 < C_; k0 += QKV_BK) {
    // -- global loads into registers (prefetch before barrier) --
    float4 xa = *(const float4*)(x + (row0 + lrow) * C_ + k0 + lseg * 4);
    float4 wreg[3];
    int kkA[3], colA[3];
#pragma unroll
    for (int i = 0; i < 3; i++) {
      int e = (t * 3 + i) * 4;              // element index in [16][192] tile
      int kk = e / QKV_BN;
      int col = e - kk * QKV_BN;
      kkA[i] = kk; colA[i] = col;
      int w = col >> 6, h = col & 63;       // which weight matrix, which head col
      const float* wp = (w == 0) ? Wq : (w == 1 ? Wk : Wv);
      wreg[i] = *(const float4*)(wp + (k0 + kk) * H_ + h);
    }

    __syncthreads();  // previous iteration's smem reads complete
    As[lseg * 4 + 0][lrow] = xa.x;
    As[lseg * 4 + 1][lrow] = xa.y;
    As[lseg * 4 + 2][lrow] = xa.z;
    As[lseg * 4 + 3][lrow] = xa.w;
#pragma unroll
    for (int i = 0; i < 3; i++)
      *(float4*)&Bs[kkA[i]][colA[i]] = wreg[i];
    __syncthreads();

#pragma unroll
    for (int kk = 0; kk < QKV_BK; kk++) {
      float4 a  = *(const float4*)&As[kk][ty * 4];
      float4 b0 = *(const float4*)&Bs[kk][tx * 12];
      float4 b1 = *(const float4*)&Bs[kk][tx * 12 + 4];
      float4 b2 = *(const float4*)&Bs[kk][tx * 12 + 8];
      float av[4] = {a.x, a.y, a.z, a.w};
      float bv[12] = {b0.x, b0.y, b0.z, b0.w,
                      b1.x, b1.y, b1.z, b1.w,
                      b2.x, b2.y, b2.z, b2.w};
#pragma unroll
      for (int i = 0; i < 4; i++)
#pragma unroll
        for (int j = 0; j < 12; j++)
          acc[i][j] += av[i] * bv[j];
    }
  }

  // -- writeback: split the 192 columns back into q / k / v --
#pragma unroll
  for (int i = 0; i < 4; i++) {
    int row = row0 + ty * 4 + i;
#pragma unroll
    for (int j = 0; j < 12; j++) {
      int n = tx * 12 + j;
      int w = n >> 6, h = n & 63;
      float* dst = (w == 0) ? g_q : (w == 1 ? g_k : g_v);
      dst[row * H_ + h] = acc[i][j];
    }
  }
}

// ---------------------------------------------------------------------------
// Kernel 2: causal flash attention, fp32, online softmax.
// One block = one (batch, 64-row query tile). Key tiles of 32, only tiles
// kt <= 2*qt + 1 are visited (causal). Heavy-first block order.
// smem: Q 64x68 + K 32x68 + V 32x68 + P 64x36 + stats = 44.8 KB (static).
// ---------------------------------------------------------------------------
__global__ __launch_bounds__(256) void attn_kernel(float* __restrict__ out) {
  __shared__ float Qs[64][68];
  __shared__ float Ks[32][68];
  __shared__ float Vs[32][68];
  __shared__ float Ps[64][36];
  __shared__ float row_m[64];
  __shared__ float row_l[64];
  __shared__ float row_alpha[64];

  const int t = threadIdx.x;
  const int bx = blockIdx.x;
  const int qt = 31 - (bx >> 3);   // heavy query tiles scheduled first
  const int b  = bx & 7;
  const int bT = b * T_;
  const int qbase = qt * 64;

  // load Q tile (64x64) once
#pragma unroll
  for (int i = 0; i < 4; i++) {
    int e4 = i * 256 + t;          // 1024 float4s total
    int r = e4 >> 4, c4 = e4 & 15;
    *(float4*)&Qs[r][c4 * 4] =
        *(const float4*)(g_q + (bT + qbase + r) * H_ + c4 * 4);
  }
  if (t < 64) { row_m[t] = -1e30f; row_l[t] = 0.f; }

  // S-phase mapping: 8 col-groups x 32 row-groups (2 rows, 4 cols each)
  const int sx = t & 7, sy = t >> 3;
  const int r0 = sy * 2;
  const int c0 = sx * 4;
  // O-phase mapping: 16 x 16 (4 rows, 4 cols each)
  const int ox = t & 15, oy = t >> 4;
  const int m0 = oy * 4, h0 = ox * 4;

  float o[4][4];
#pragma unroll
  for (int i = 0; i < 4; i++)
#pragma unroll
    for (int j = 0; j < 4; j++) o[i][j] = 0.f;

  const int nkt = 2 * qt + 2;
  for (int kt = 0; kt < nkt; kt++) {
    const int kbase = kt * 32;

    // prefetch K/V tile into registers
    float4 kreg[2], vreg[2];
#pragma unroll
    for (int i = 0; i < 2; i++) {
      int e4 = i * 256 + t;
      int r = e4 >> 4, c4 = e4 & 15;
      kreg[i] = *(const float4*)(g_k + (bT + kbase + r) * H_ + c4 * 4);
      vreg[i] = *(const float4*)(g_v + (bT + kbase + r) * H_ + c4 * 4);
    }
    __syncthreads();   // previous iteration's Ks/Vs/Ps reads done
#pragma unroll
    for (int i = 0; i < 2; i++) {
      int e4 = i * 256 + t;
      int r = e4 >> 4, c4 = e4 & 15;
      *(float4*)&Ks[r][c4 * 4] = kreg[i];
      *(float4*)&Vs[r][c4 * 4] = vreg[i];
    }
    __syncthreads();

    // ---- S = Q K^T for this tile (each thread: 2 rows x 4 cols) ----
    float s[2][4] = {{0.f, 0.f, 0.f, 0.f}, {0.f, 0.f, 0.f, 0.f}};
#pragma unroll
    for (int k4 = 0; k4 < 16; k4++) {
      float4 q0 = *(const float4*)&Qs[r0][k4 * 4];
      float4 q1 = *(const float4*)&Qs[r0 + 1][k4 * 4];
#pragma unroll
      for (int j = 0; j < 4; j++) {
        float4 kv = *(const float4*)&Ks[c0 + j][k4 * 4];
        s[0][j] += q0.x * kv.x + q0.y * kv.y + q0.z * kv.z + q0.w * kv.w;
        s[1][j] += q1.x * kv.x + q1.y * kv.y + q1.z * kv.z + q1.w * kv.w;
      }
    }

    // ---- online softmax update ----
#pragma unroll
    for (int i = 0; i < 2; i++) {
      int r = r0 + i;
      int qidx = qbase + r;
      float mloc = -1e30f;
#pragma unroll
      for (int j = 0; j < 4; j++) {
        float sv = s[i][j] * 0.125f;              // * H^-0.5
        if (kbase + c0 + j > qidx) sv = -1e30f;   // causal mask
        s[i][j] = sv;
        mloc = fmaxf(mloc, sv);
      }
      mloc = fmaxf(mloc, __shfl_xor_sync(0xffffffffu, mloc, 1));
      mloc = fmaxf(mloc, __shfl_xor_sync(0xffffffffu, mloc, 2));
      mloc = fmaxf(mloc, __shfl_xor_sync(0xffffffffu, mloc, 4));
      float mold = row_m[r];
      float mnew = fmaxf(mold, mloc);
      float psum = 0.f;
#pragma unroll
      for (int j = 0; j < 4; j++) {
        float p = __expf(s[i][j] - mnew);
        Ps[r][c0 + j] = p;
        psum += p;
      }
      psum += __shfl_xor_sync(0xffffffffu, psum, 1);
      psum += __shfl_xor_sync(0xffffffffu, psum, 2);
      psum += __shfl_xor_sync(0xffffffffu, psum, 4);
      if (sx == 0) {
        float alpha = __expf(mold - mnew);
        row_m[r] = mnew;
        row_l[r] = row_l[r] * alpha + psum;
        row_alpha[r] = alpha;
      }
    }
    __syncthreads();

    // ---- O = alpha * O + P V (each thread: 4 rows x 4 cols) ----
    float av[4];
#pragma unroll
    for (int i = 0; i < 4; i++) av[i] = row_alpha[m0 + i];
#pragma unroll
    for (int i = 0; i < 4; i++)
#pragma unroll
      for (int j = 0; j < 4; j++) o[i][j] *= av[i];

#pragma unroll
    for (int sI = 0; sI < 32; sI++) {
      float4 v = *(const float4*)&Vs[sI][h0];
#pragma unroll
      for (int i = 0; i < 4; i++) {
        float p = Ps[m0 + i][sI];
        o[i][0] += p * v.x;
        o[i][1] += p * v.y;
        o[i][2] += p * v.z;
        o[i][3] += p * v.w;
      }
    }
    // (loop-top __syncthreads protects Ks/Vs/Ps reuse)
  }

  // ---- final normalize + store ----
#pragma unroll
  for (int i = 0; i < 4; i++) {
    float inv = 1.0f / row_l[m0 + i];
    float4 res;
    res.x = o[i][0] * inv;
    res.y = o[i][1] * inv;
    res.z = o[i][2] * inv;
    res.w = o[i][3] * inv;
    *(float4*)(out + (bT + qbase + m0 + i) * H_ + h0) = res;
  }
}

// ---------------------------------------------------------------------------
extern "C" void kernel_launch(void* const* d_in, const int* in_sizes, int n_in,
                              void* d_out, int out_size) {
  const float* x  = (const float*)d_in[0];
  const float* Wq = (const float*)d_in[1];
  const float* Wk = (const float*)d_in[2];
  const float* Wv = (const float*)d_in[3];
  float* out = (float*)d_out;

  qkv_kernel<<<M_TOTAL / QKV_BM, 256>>>(x, Wq, Wk, Wv);   // 256 blocks
  attn_kernel<<<B_ * 32, 256>>>(out);                     // 256 blocks
}

// round 2
// speedup vs baseline: 1.7730x; 1.7730x over previous
#include <cuda_runtime.h>
#include <cuda_bf16.h>

#define B_ 8
#define T_ 2048
#define C_ 1024
#define H_ 64
#define M_TOTAL (B_ * T_)   // 16384 rows

// Scratch for q, k, v projections (allocation-free rule: __device__ globals)
__device__ float g_q[M_TOTAL * H_];
__device__ float g_k[M_TOTAL * H_];
__device__ float g_v[M_TOTAL * H_];

// ---------------------------------------------------------------------------
// Kernel 1: fused QKV projection (unchanged — already ~near fp32 roofline).
// ---------------------------------------------------------------------------
#define QKV_BM 64
#define QKV_BK 16
#define QKV_BN 192

__global__ __launch_bounds__(256) void qkv_kernel(
    const float* __restrict__ x,
    const float* __restrict__ Wq,
    const float* __restrict__ Wk,
    const float* __restrict__ Wv) {
  __shared__ float As[QKV_BK][68];
  __shared__ float Bs[QKV_BK][QKV_BN];

  const int t = threadIdx.x;
  const int tx = t & 15;
  const int ty = t >> 4;
  const int row0 = blockIdx.x * QKV_BM;
  const int lrow = t >> 2;
  const int lseg = t & 3;

  float acc[4][12];
#pragma unroll
  for (int i = 0; i < 4; i++)
#pragma unroll
    for (int j = 0; j < 12; j++) acc[i][j] = 0.f;

  for (int k0 = 0; k0 < C_; k0 += QKV_BK) {
    float4 xa = *(const float4*)(x + (row0 + lrow) * C_ + k0 + lseg * 4);
    float4 wreg[3];
    int kkA[3], colA[3];
#pragma unroll
    for (int i = 0; i < 3; i++) {
      int e = (t * 3 + i) * 4;
      int kk = e / QKV_BN;
      int col = e - kk * QKV_BN;
      kkA[i] = kk; colA[i] = col;
      int w = col >> 6, h = col & 63;
      const float* wp = (w == 0) ? Wq : (w == 1 ? Wk : Wv);
      wreg[i] = *(const float4*)(wp + (k0 + kk) * H_ + h);
    }

    __syncthreads();
    As[lseg * 4 + 0][lrow] = xa.x;
    As[lseg * 4 + 1][lrow] = xa.y;
    As[lseg * 4 + 2][lrow] = xa.z;
    As[lseg * 4 + 3][lrow] = xa.w;
#pragma unroll
    for (int i = 0; i < 3; i++)
      *(float4*)&Bs[kkA[i]][colA[i]] = wreg[i];
    __syncthreads();

#pragma unroll
    for (int kk = 0; kk < QKV_BK; kk++) {
      float4 a  = *(const float4*)&As[kk][ty * 4];
      float4 b0 = *(const float4*)&Bs[kk][tx * 12];
      float4 b1 = *(const float4*)&Bs[kk][tx * 12 + 4];
      float4 b2 = *(const float4*)&Bs[kk][tx * 12 + 8];
      float av[4] = {a.x, a.y, a.z, a.w};
      float bv[12] = {b0.x, b0.y, b0.z, b0.w,
                      b1.x, b1.y, b1.z, b1.w,
                      b2.x, b2.y, b2.z, b2.w};
#pragma unroll
      for (int i = 0; i < 4; i++)
#pragma unroll
        for (int j = 0; j < 12; j++)
          acc[i][j] += av[i] * bv[j];
    }
  }

#pragma unroll
  for (int i = 0; i < 4; i++) {
    int row = row0 + ty * 4 + i;
#pragma unroll
    for (int j = 0; j < 12; j++) {
      int n = tx * 12 + j;
      int w = n >> 6, h = n & 63;
      float* dst = (w == 0) ? g_q : (w == 1 ? g_k : g_v);
      dst[row * H_ + h] = acc[i][j];
    }
  }
}

// ---------------------------------------------------------------------------
// Kernel 2: causal flash attention, fp32, online softmax.
// QT=64, KT=64. 256 threads = 16x16 grid; thread tile 4x4 with SCATTERED
// mapping: rows m = ty+16i, cols c = tx+16j. This makes Q/P smem reads
// 2-address broadcasts and spreads K reads across all bank quads.
// Softmax stats (m, l, alpha) live in registers (row owned by one warp).
// smem (dynamic): Q,K,V,P each 64x68 fp32 = 69,632 B.
// ---------------------------------------------------------------------------
#define AT_STRIDE 68
#define AT_TILE   (64 * AT_STRIDE)          // floats per region
#define AT_SMEM_BYTES (4 * AT_TILE * 4)     // 69632 bytes

__global__ __launch_bounds__(256) void attn_kernel(float* __restrict__ out) {
  extern __shared__ float sm[];
  float* Qs = sm;
  float* Ks = sm + AT_TILE;
  float* Vs = sm + 2 * AT_TILE;
  float* Ps = sm + 3 * AT_TILE;
#define QS(r, c) Qs[(r) * AT_STRIDE + (c)]
#define KS(r, c) Ks[(r) * AT_STRIDE + (c)]
#define VS(r, c) Vs[(r) * AT_STRIDE + (c)]
#define PS(r, c) Ps[(r) * AT_STRIDE + (c)]

  const int t = threadIdx.x;
  const int bx = blockIdx.x;
  const int qt = 31 - (bx >> 3);   // heavy query tiles first
  const int b  = bx & 7;
  const int bT = b * T_;
  const int qbase = qt * 64;

  const int tx = t & 15;
  const int ty = t >> 4;

  // load Q tile (64x64) once
#pragma unroll
  for (int i = 0; i < 4; i++) {
    int e4 = i * 256 + t;
    int r = e4 >> 4, c4 = e4 & 15;
    *(float4*)&QS(r, c4 * 4) =
        *(const float4*)(g_q + (bT + qbase + r) * H_ + c4 * 4);
  }

  float o[4][4];
  float m_reg[4], l_reg[4];
#pragma unroll
  for (int i = 0; i < 4; i++) {
    m_reg[i] = -1e30f;
    l_reg[i] = 0.f;
#pragma unroll
    for (int j = 0; j < 4; j++) o[i][j] = 0.f;
  }

  const int nkt = qt + 1;
  for (int kt = 0; kt < nkt; kt++) {
    const int kbase = kt * 64;

    // prefetch K/V tile (64x64 each) into registers
    float4 kreg[4], vreg[4];
#pragma unroll
    for (int i = 0; i < 4; i++) {
      int e4 = i * 256 + t;
      int r = e4 >> 4, c4 = e4 & 15;
      kreg[i] = *(const float4*)(g_k + (bT + kbase + r) * H_ + c4 * 4);
      vreg[i] = *(const float4*)(g_v + (bT + kbase + r) * H_ + c4 * 4);
    }
    __syncthreads();   // prev iter's Ks/Vs/Ps reads complete
#pragma unroll
    for (int i = 0; i < 4; i++) {
      int e4 = i * 256 + t;
      int r = e4 >> 4, c4 = e4 & 15;
      *(float4*)&KS(r, c4 * 4) = kreg[i];
      *(float4*)&VS(r, c4 * 4) = vreg[i];
    }
    __syncthreads();

    // ---- S = Q K^T : thread computes rows ty+16i x cols tx+16j ----
    float s[4][4];
#pragma unroll
    for (int i = 0; i < 4; i++)
#pragma unroll
      for (int j = 0; j < 4; j++) s[i][j] = 0.f;

#pragma unroll
    for (int k4 = 0; k4 < 16; k4++) {
      float4 q[4], kf[4];
#pragma unroll
      for (int i = 0; i < 4; i++) q[i] = *(const float4*)&QS(ty + 16 * i, k4 * 4);
#pragma unroll
      for (int j = 0; j < 4; j++) kf[j] = *(const float4*)&KS(tx + 16 * j, k4 * 4);
#pragma unroll
      for (int i = 0; i < 4; i++)
#pragma unroll
        for (int j = 0; j < 4; j++)
          s[i][j] += q[i].x * kf[j].x + q[i].y * kf[j].y +
                     q[i].z * kf[j].z + q[i].w * kf[j].w;
    }

    // ---- online softmax (stats in registers; row = one warp's 16 tx lanes) --
    float alpha_reg[4];
#pragma unroll
    for (int i = 0; i < 4; i++) {
      const int r = ty + 16 * i;
      const int qidx = qbase + r;
      float mloc = -1e30f;
#pragma unroll
      for (int j = 0; j < 4; j++) {
        float sv = s[i][j] * 0.125f;               // * H^-0.5
        if (kbase + tx + 16 * j > qidx) sv = -1e30f;
        s[i][j] = sv;
        mloc = fmaxf(mloc, sv);
      }
      mloc = fmaxf(mloc, __shfl_xor_sync(0xffffffffu, mloc, 1));
      mloc = fmaxf(mloc, __shfl_xor_sync(0xffffffffu, mloc, 2));
      mloc = fmaxf(mloc, __shfl_xor_sync(0xffffffffu, mloc, 4));
      mloc = fmaxf(mloc, __shfl_xor_sync(0xffffffffu, mloc, 8));
      float mnew = fmaxf(m_reg[i], mloc);
      float alpha = __expf(m_reg[i] - mnew);
      float psum = 0.f;
#pragma unroll
      for (int j = 0; j < 4; j++) {
        float p = __expf(s[i][j] - mnew);
        PS(r, tx + 16 * j) = p;
        psum += p;
      }
      psum += __shfl_xor_sync(0xffffffffu, psum, 1);
      psum += __shfl_xor_sync(0xffffffffu, psum, 2);
      psum += __shfl_xor_sync(0xffffffffu, psum, 4);
      psum += __shfl_xor_sync(0xffffffffu, psum, 8);
      l_reg[i] = l_reg[i] * alpha + psum;
      m_reg[i] = mnew;
      alpha_reg[i] = alpha;
    }
    __syncthreads();   // Ps visible to all

    // ---- O = alpha * O + P V : rows ty+16i, h-cols tx*4..tx*4+3 ----
#pragma unroll
    for (int i = 0; i < 4; i++)
#pragma unroll
      for (int j = 0; j < 4; j++) o[i][j] *= alpha_reg[i];

#pragma unroll
    for (int s4 = 0; s4 < 16; s4++) {
      float4 p[4], v[4];
#pragma unroll
      for (int i = 0; i < 4; i++) p[i] = *(const float4*)&PS(ty + 16 * i, s4 * 4);
#pragma unroll
      for (int u = 0; u < 4; u++) v[u] = *(const float4*)&VS(s4 * 4 + u, tx * 4);
#pragma unroll
      for (int i = 0; i < 4; i++) {
        o[i][0] += p[i].x * v[0].x + p[i].y * v[1].x + p[i].z * v[2].x + p[i].w * v[3].x;
        o[i][1] += p[i].x * v[0].y + p[i].y * v[1].y + p[i].z * v[2].y + p[i].w * v[3].y;
        o[i][2] += p[i].x * v[0].z + p[i].y * v[1].z + p[i].z * v[2].z + p[i].w * v[3].z;
        o[i][3] += p[i].x * v[0].w + p[i].y * v[1].w + p[i].z * v[2].w + p[i].w * v[3].w;
      }
    }
  }

  // ---- final normalize + store (rows ty+16i, cols tx*4) ----
#pragma unroll
  for (int i = 0; i < 4; i++) {
    float inv = 1.0f / l_reg[i];
    float4 res;
    res.x = o[i][0] * inv;
    res.y = o[i][1] * inv;
    res.z = o[i][2] * inv;
    res.w = o[i][3] * inv;
    *(float4*)(out + (bT + qbase + ty + 16 * i) * H_ + tx * 4) = res;
  }
}

// ---------------------------------------------------------------------------
extern "C" void kernel_launch(void* const* d_in, const int* in_sizes, int n_in,
                              void* d_out, int out_size) {
  const float* x  = (const float*)d_in[0];
  const float* Wq = (const float*)d_in[1];
  const float* Wk = (const float*)d_in[2];
  const float* Wv = (const float*)d_in[3];
  float* out = (float*)d_out;

  cudaFuncSetAttribute(attn_kernel,
                       cudaFuncAttributeMaxDynamicSharedMemorySize,
                       AT_SMEM_BYTES);

  qkv_kernel<<<M_TOTAL / QKV_BM, 256>>>(x, Wq, Wk, Wv);        // 256 blocks
  attn_kernel<<<B_ * 32, 256, AT_SMEM_BYTES>>>(out);           // 256 blocks
}

// round 3
// speedup vs baseline: 2.4952x; 1.4073x over previous
#include <cuda_runtime.h>
#include <cuda_bf16.h>

#define B_ 8
#define T_ 2048
#define C_ 1024
#define H_ 64
#define M_TOTAL (B_ * T_)   // 16384 rows

// bf16 hi/lo split scratch (allocation-free rule: __device__ globals)
__device__ __align__(16) __nv_bfloat16 g_qh[M_TOTAL * H_];
__device__ __align__(16) __nv_bfloat16 g_ql[M_TOTAL * H_];
__device__ __align__(16) __nv_bfloat16 g_kh[M_TOTAL * H_];
__device__ __align__(16) __nv_bfloat16 g_kl[M_TOTAL * H_];
// V stored transposed per batch: [b][h][t]
__device__ __align__(16) __nv_bfloat16 g_vth[B_ * H_ * T_];
__device__ __align__(16) __nv_bfloat16 g_vtl[B_ * H_ * T_];

// ---------------------------------------------------------------------------
// Kernel 1: fused QKV projection (fp32 GEMM, near roofline) + bf16 hi/lo split
// writeback; V written transposed.
// ---------------------------------------------------------------------------
#define QKV_BM 64
#define QKV_BK 16
#define QKV_BN 192

__global__ __launch_bounds__(256) void qkv_kernel(
    const float* __restrict__ x,
    const float* __restrict__ Wq,
    const float* __restrict__ Wk,
    const float* __restrict__ Wv) {
  __shared__ float As[QKV_BK][68];
  __shared__ float Bs[QKV_BK][QKV_BN];

  const int t = threadIdx.x;
  const int tx = t & 15;
  const int ty = t >> 4;
  const int row0 = blockIdx.x * QKV_BM;
  const int lrow = t >> 2;
  const int lseg = t & 3;

  float acc[4][12];
#pragma unroll
  for (int i = 0; i < 4; i++)
#pragma unroll
    for (int j = 0; j < 12; j++) acc[i][j] = 0.f;

  for (int k0 = 0; k0 < C_; k0 += QKV_BK) {
    float4 xa = *(const float4*)(x + (row0 + lrow) * C_ + k0 + lseg * 4);
    float4 wreg[3];
    int kkA[3], colA[3];
#pragma unroll
    for (int i = 0; i < 3; i++) {
      int e = (t * 3 + i) * 4;
      int kk = e / QKV_BN;
      int col = e - kk * QKV_BN;
      kkA[i] = kk; colA[i] = col;
      int w = col >> 6, h = col & 63;
      const float* wp = (w == 0) ? Wq : (w == 1 ? Wk : Wv);
      wreg[i] = *(const float4*)(wp + (k0 + kk) * H_ + h);
    }

    __syncthreads();
    As[lseg * 4 + 0][lrow] = xa.x;
    As[lseg * 4 + 1][lrow] = xa.y;
    As[lseg * 4 + 2][lrow] = xa.z;
    As[lseg * 4 + 3][lrow] = xa.w;
#pragma unroll
    for (int i = 0; i < 3; i++)
      *(float4*)&Bs[kkA[i]][colA[i]] = wreg[i];
    __syncthreads();

#pragma unroll
    for (int kk = 0; kk < QKV_BK; kk++) {
      float4 a  = *(const float4*)&As[kk][ty * 4];
      float4 b0 = *(const float4*)&Bs[kk][tx * 12];
      float4 b1 = *(const float4*)&Bs[kk][tx * 12 + 4];
      float4 b2 = *(const float4*)&Bs[kk][tx * 12 + 8];
      float av[4] = {a.x, a.y, a.z, a.w};
      float bv[12] = {b0.x, b0.y, b0.z, b0.w,
                      b1.x, b1.y, b1.z, b1.w,
                      b2.x, b2.y, b2.z, b2.w};
#pragma unroll
      for (int i = 0; i < 4; i++)
#pragma unroll
        for (int j = 0; j < 12; j++)
          acc[i][j] += av[i] * bv[j];
    }
  }

  // writeback: split into bf16 hi/lo; q,k row-major; v transposed [b][h][t]
#pragma unroll
  for (int i = 0; i < 4; i++) {
    int row = row0 + ty * 4 + i;
    int bb = row >> 11;          // batch
    int tt = row & 2047;         // position within batch
#pragma unroll
    for (int j = 0; j < 12; j++) {
      int n = tx * 12 + j;
      int w = n >> 6, h = n & 63;
      float a = acc[i][j];
      __nv_bfloat16 hi = __float2bfloat16(a);
      __nv_bfloat16 lo = __float2bfloat16(a - __bfloat162float(hi));
      if (w == 0) {
        g_qh[row * H_ + h] = hi; g_ql[row * H_ + h] = lo;
      } else if (w == 1) {
        g_kh[row * H_ + h] = hi; g_kl[row * H_ + h] = lo;
      } else {
        int idx = (bb * H_ + h) * T_ + tt;
        g_vth[idx] = hi; g_vtl[idx] = lo;
      }
    }
  }
}

// ---------------------------------------------------------------------------
// Kernel 2: causal flash attention on tensor cores.
// bf16 mma.sync m16n8k16 with 2-term (hi/lo) split: hi*hi + hi*lo + lo*hi.
// Block: 64 q-rows x full key sweep in 64-key tiles. 8 warps = 4(M) x 2(N).
// Q A-fragments register-resident for the whole block. K, V^T, P staged in
// smem with stride 72 (conflict-free for fragment pattern).
// ---------------------------------------------------------------------------
#define SKS 72                       // bf16 element stride of smem tiles
#define TILE_ELEMS (64 * SKS)        // 4608 bf16 per tile
#define ATT_SMEM_BYTES (6 * TILE_ELEMS * 2 + 256 * 4)   // 56320

__device__ __forceinline__ void mma_bf16(float d[4], const unsigned a[4],
                                         unsigned b0, unsigned b1) {
  asm volatile(
      "mma.sync.aligned.m16n8k16.row.col.f32.bf16.bf16.f32 "
      "{%0,%1,%2,%3}, {%4,%5,%6,%7}, {%8,%9}, {%0,%1,%2,%3};\n"
      : "+f"(d[0]), "+f"(d[1]), "+f"(d[2]), "+f"(d[3])
      : "r"(a[0]), "r"(a[1]), "r"(a[2]), "r"(a[3]), "r"(b0), "r"(b1));
}

#define LDU(p) (*(const unsigned*)&(p))

__global__ __launch_bounds__(256, 2) void attn_kernel(float* __restrict__ out) {
  extern __shared__ __nv_bfloat16 smb[];
  __nv_bfloat16* Kh  = smb;
  __nv_bfloat16* Kl  = smb + TILE_ELEMS;
  __nv_bfloat16* VTh = smb + 2 * TILE_ELEMS;
  __nv_bfloat16* VTl = smb + 3 * TILE_ELEMS;
  __nv_bfloat16* Ph  = smb + 4 * TILE_ELEMS;
  __nv_bfloat16* Pl  = smb + 5 * TILE_ELEMS;
  float* redmax = (float*)(smb + 6 * TILE_ELEMS);   // [2][64]
  float* redsum = redmax + 128;                     // [2][64]

  const int t = threadIdx.x;
  const int warp = t >> 5, lane = t & 31;
  const int g = lane >> 2, c = lane & 3;
  const int wm = warp >> 1, wn = warp & 1;
  const int bx = blockIdx.x;
  const int qt = 31 - (bx >> 3);     // heavy query tiles first
  const int b  = bx & 7;
  const int bT = b * T_;
  const int qbase = qt * 64;

  // ---- Q A-fragments, register-resident (rows wm*16+g / +8) ----
  unsigned qfh[4][4], qfl[4][4];
  {
    const unsigned* qhp = (const unsigned*)g_qh;
    const unsigned* qlp = (const unsigned*)g_ql;
    int r0 = (bT + qbase + wm * 16 + g) * 32;   // 32 uints per 64-col row
    int r8 = r0 + 8 * 32;
#pragma unroll
    for (int ks = 0; ks < 4; ks++) {
      int off = ks * 8 + c;
      qfh[ks][0] = qhp[r0 + off];
      qfh[ks][1] = qhp[r8 + off];
      qfh[ks][2] = qhp[r0 + off + 4];
      qfh[ks][3] = qhp[r8 + off + 4];
      qfl[ks][0] = qlp[r0 + off];
      qfl[ks][1] = qlp[r8 + off];
      qfl[ks][2] = qlp[r0 + off + 4];
      qfl[ks][3] = qlp[r8 + off + 4];
    }
  }

  float o[4][4];
#pragma unroll
  for (int j = 0; j < 4; j++)
#pragma unroll
    for (int r = 0; r < 4; r++) o[j][r] = 0.f;
  float m0 = -1e30f, m1 = -1e30f, l0 = 0.f, l1 = 0.f;

  const unsigned* khp  = (const unsigned*)g_kh;
  const unsigned* klp  = (const unsigned*)g_kl;
  const unsigned* vthp = (const unsigned*)g_vth;
  const unsigned* vtlp = (const unsigned*)g_vtl;

  // per-thread staging slot: row = i*8+warp, uint-col = lane
  unsigned pk[16], pv[16];
  {
    // prefetch tile 0
#pragma unroll
    for (int i = 0; i < 8; i++) {
      int r = i * 8 + warp;
      pk[i]     = khp[(bT + r) * 32 + lane];
      pk[i + 8] = klp[(bT + r) * 32 + lane];
      pv[i]     = vthp[(b * 64 + r) * 1024 + lane];
      pv[i + 8] = vtlp[(b * 64 + r) * 1024 + lane];
    }
  }

  const int nkt = qt + 1;
  for (int kt = 0; kt < nkt; kt++) {
    __syncthreads();   // (A) prior-iter smem reads complete
#pragma unroll
    for (int i = 0; i < 8; i++) {
      int so = (i * 8 + warp) * SKS + lane * 2;
      *(unsigned*)&Kh[so]  = pk[i];
      *(unsigned*)&Kl[so]  = pk[i + 8];
      *(unsigned*)&VTh[so] = pv[i];
      *(unsigned*)&VTl[so] = pv[i + 8];
    }
    __syncthreads();   // (B) tiles visible

    if (kt + 1 < nkt) {
      int kb2 = (kt + 1) * 64;
#pragma unroll
      for (int i = 0; i < 8; i++) {
        int r = i * 8 + warp;
        pk[i]     = khp[(bT + kb2 + r) * 32 + lane];
        pk[i + 8] = klp[(bT + kb2 + r) * 32 + lane];
        pv[i]     = vthp[(b * 64 + r) * 1024 + (kt + 1) * 32 + lane];
        pv[i + 8] = vtlp[(b * 64 + r) * 1024 + (kt + 1) * 32 + lane];
      }
    }

    // ---- S = Q K^T (warp tile: rows wm*16.., cols wn*32.. as 4 n8 tiles) ----
    float s[4][4];
#pragma unroll
    for (int j = 0; j < 4; j++)
#pragma unroll
      for (int r = 0; r < 4; r++) s[j][r] = 0.f;

#pragma unroll
    for (int ks = 0; ks < 4; ks++) {
#pragma unroll
      for (int j = 0; j < 4; j++) {
        int nr = (wn * 32 + j * 8 + g) * SKS + ks * 16 + 2 * c;
        unsigned bh0 = LDU(Kh[nr]);
        unsigned bh1 = LDU(Kh[nr + 8]);
        unsigned bl0 = LDU(Kl[nr]);
        unsigned bl1 = LDU(Kl[nr + 8]);
        mma_bf16(s[j], qfh[ks], bh0, bh1);
        mma_bf16(s[j], qfh[ks], bl0, bl1);
        mma_bf16(s[j], qfl[ks], bh0, bh1);
      }
    }

    // ---- scale + causal mask (only diagonal tile is partial) ----
    const int kbase = kt * 64;
    const int qi0 = qbase + wm * 16 + g;
    const int qi1 = qi0 + 8;
#pragma unroll
    for (int j = 0; j < 4; j++) {
      s[j][0] *= 0.125f; s[j][1] *= 0.125f;
      s[j][2] *= 0.125f; s[j][3] *= 0.125f;
      if (kt == qt) {
        int col0 = kbase + wn * 32 + j * 8 + 2 * c;
        if (col0     > qi0) s[j][0] = -1e30f;
        if (col0 + 1 > qi0) s[j][1] = -1e30f;
        if (col0     > qi1) s[j][2] = -1e30f;
        if (col0 + 1 > qi1) s[j][3] = -1e30f;
      }
    }

    // ---- online softmax ----
    float mx0 = -1e30f, mx1 = -1e30f;
#pragma unroll
    for (int j = 0; j < 4; j++) {
      mx0 = fmaxf(mx0, fmaxf(s[j][0], s[j][1]));
      mx1 = fmaxf(mx1, fmaxf(s[j][2], s[j][3]));
    }
    mx0 = fmaxf(mx0, __shfl_xor_sync(0xffffffffu, mx0, 1));
    mx0 = fmaxf(mx0, __shfl_xor_sync(0xffffffffu, mx0, 2));
    mx1 = fmaxf(mx1, __shfl_xor_sync(0xffffffffu, mx1, 1));
    mx1 = fmaxf(mx1, __shfl_xor_sync(0xffffffffu, mx1, 2));
    if (c == 0) {
      redmax[wn * 64 + wm * 16 + g]     = mx0;
      redmax[wn * 64 + wm * 16 + 8 + g] = mx1;
    }
    __syncthreads();   // (C)
    float M0 = fmaxf(m0, fmaxf(mx0, redmax[(1 - wn) * 64 + wm * 16 + g]));
    float M1 = fmaxf(m1, fmaxf(mx1, redmax[(1 - wn) * 64 + wm * 16 + 8 + g]));
    float a0 = __expf(m0 - M0);
    float a1 = __expf(m1 - M1);
    m0 = M0; m1 = M1;

    float ps0 = 0.f, ps1 = 0.f;
#pragma unroll
    for (int j = 0; j < 4; j++) {
      float p00 = __expf(s[j][0] - M0);
      float p01 = __expf(s[j][1] - M0);
      float p10 = __expf(s[j][2] - M1);
      float p11 = __expf(s[j][3] - M1);
      ps0 += p00 + p01;
      ps1 += p10 + p11;
      // pack hi/lo and store P fragments to smem
      int pr0 = (wm * 16 + g) * SKS + wn * 32 + j * 8 + 2 * c;
      int pr1 = pr0 + 8 * SKS;
      __nv_bfloat162 h2 = __floats2bfloat162_rn(p00, p01);
      float2 hf = __bfloat1622float2(h2);
      __nv_bfloat162 l2 = __floats2bfloat162_rn(p00 - hf.x, p01 - hf.y);
      *(unsigned*)&Ph[pr0] = *(unsigned*)&h2;
      *(unsigned*)&Pl[pr0] = *(unsigned*)&l2;
      __nv_bfloat162 h3 = __floats2bfloat162_rn(p10, p11);
      float2 hg = __bfloat1622float2(h3);
      __nv_bfloat162 l3 = __floats2bfloat162_rn(p10 - hg.x, p11 - hg.y);
      *(unsigned*)&Ph[pr1] = *(unsigned*)&h3;
      *(unsigned*)&Pl[pr1] = *(unsigned*)&l3;
    }
    ps0 += __shfl_xor_sync(0xffffffffu, ps0, 1);
    ps0 += __shfl_xor_sync(0xffffffffu, ps0, 2);
    ps1 += __shfl_xor_sync(0xffffffffu, ps1, 1);
    ps1 += __shfl_xor_sync(0xffffffffu, ps1, 2);
    if (c == 0) {
      redsum[wn * 64 + wm * 16 + g]     = ps0;
      redsum[wn * 64 + wm * 16 + 8 + g] = ps1;
    }
    __syncthreads();   // (D) P tiles + sums visible
    l0 = l0 * a0 + ps0 + redsum[(1 - wn) * 64 + wm * 16 + g];
    l1 = l1 * a1 + ps1 + redsum[(1 - wn) * 64 + wm * 16 + 8 + g];

    // ---- O = diag(alpha) O + P V ----
#pragma unroll
    for (int j = 0; j < 4; j++) {
      o[j][0] *= a0; o[j][1] *= a0;
      o[j][2] *= a1; o[j][3] *= a1;
    }
#pragma unroll
    for (int ks = 0; ks < 4; ks++) {
      unsigned pah[4], pal[4];
      int ar = (wm * 16 + g) * SKS + ks * 16 + 2 * c;
      pah[0] = LDU(Ph[ar]);
      pah[1] = LDU(Ph[ar + 8 * SKS]);
      pah[2] = LDU(Ph[ar + 8]);
      pah[3] = LDU(Ph[ar + 8 * SKS + 8]);
      pal[0] = LDU(Pl[ar]);
      pal[1] = LDU(Pl[ar + 8 * SKS]);
      pal[2] = LDU(Pl[ar + 8]);
      pal[3] = LDU(Pl[ar + 8 * SKS + 8]);
#pragma unroll
      for (int j = 0; j < 4; j++) {
        int br = (wn * 32 + j * 8 + g) * SKS + ks * 16 + 2 * c;
        unsigned vh0 = LDU(VTh[br]);
        unsigned vh1 = LDU(VTh[br + 8]);
        unsigned vl0 = LDU(VTl[br]);
        unsigned vl1 = LDU(VTl[br + 8]);
        mma_bf16(o[j], pah, vh0, vh1);
        mma_bf16(o[j], pah, vl0, vl1);
        mma_bf16(o[j], pal, vh0, vh1);
      }
    }
  }

  // ---- epilogue: normalize + store ----
  float i0 = 1.0f / l0, i1 = 1.0f / l1;
  int ob0 = (bT + qbase + wm * 16 + g) * H_ + wn * 32;
  int ob1 = ob0 + 8 * H_;
#pragma unroll
  for (int j = 0; j < 4; j++) {
    float2 r0 = make_float2(o[j][0] * i0, o[j][1] * i0);
    float2 r1 = make_float2(o[j][2] * i1, o[j][3] * i1);
    *(float2*)&out[ob0 + j * 8 + 2 * c] = r0;
    *(float2*)&out[ob1 + j * 8 + 2 * c] = r1;
  }
}

// ---------------------------------------------------------------------------
extern "C" void kernel_launch(void* const* d_in, const int* in_sizes, int n_in,
                              void* d_out, int out_size) {
  const float* x  = (const float*)d_in[0];
  const float* Wq = (const float*)d_in[1];
  const float* Wk = (const float*)d_in[2];
  const float* Wv = (const float*)d_in[3];
  float* out = (float*)d_out;

  cudaFuncSetAttribute(attn_kernel,
                       cudaFuncAttributeMaxDynamicSharedMemorySize,
                       ATT_SMEM_BYTES);

  qkv_kernel<<<M_TOTAL / QKV_BM, 256>>>(x, Wq, Wk, Wv);     // 256 blocks
  attn_kernel<<<B_ * 32, 256, ATT_SMEM_BYTES>>>(out);       // 256 blocks
}

// round 4
// speedup vs baseline: 2.6042x; 1.0437x over previous
#include <cuda_runtime.h>
#include <cuda_bf16.h>

#define B_ 8
#define T_ 2048
#define C_ 1024
#define H_ 64
#define M_TOTAL (B_ * T_)   // 16384 rows

// bf16 hi/lo split scratch (allocation-free rule: __device__ globals)
__device__ __align__(16) __nv_bfloat16 g_qh[M_TOTAL * H_];
__device__ __align__(16) __nv_bfloat16 g_ql[M_TOTAL * H_];
__device__ __align__(16) __nv_bfloat16 g_kh[M_TOTAL * H_];
__device__ __align__(16) __nv_bfloat16 g_kl[M_TOTAL * H_];
// V stored transposed per batch: [b][h][t]
__device__ __align__(16) __nv_bfloat16 g_vth[B_ * H_ * T_];
__device__ __align__(16) __nv_bfloat16 g_vtl[B_ * H_ * T_];
// Fused weight, transposed + split: row n = {q0..63, k0..63, v0..63}, k-major
__device__ __align__(16) __nv_bfloat16 g_wth[192 * 1024];
__device__ __align__(16) __nv_bfloat16 g_wtl[192 * 1024];

__device__ __forceinline__ void mma_bf16(float d[4], const unsigned a[4],
                                         unsigned b0, unsigned b1) {
  asm volatile(
      "mma.sync.aligned.m16n8k16.row.col.f32.bf16.bf16.f32 "
      "{%0,%1,%2,%3}, {%4,%5,%6,%7}, {%8,%9}, {%0,%1,%2,%3};\n"
      : "+f"(d[0]), "+f"(d[1]), "+f"(d[2]), "+f"(d[3])
      : "r"(a[0]), "r"(a[1]), "r"(a[2]), "r"(a[3]), "r"(b0), "r"(b1));
}

#define LDU(p) (*(const unsigned*)&(p))

// ---------------------------------------------------------------------------
// Kernel 0: transpose + hi/lo split weights into WT[192][1024] (one-shot, ~3us)
// ---------------------------------------------------------------------------
__global__ __launch_bounds__(256) void wsplit_kernel(
    const float* __restrict__ Wq, const float* __restrict__ Wk,
    const float* __restrict__ Wv) {
  const int n = blockIdx.x;          // 0..191
  const int w = n >> 6, h = n & 63;
  const float* W = (w == 0) ? Wq : (w == 1 ? Wk : Wv);
  for (int k = threadIdx.x; k < C_; k += 256) {
    float v = W[k * H_ + h];
    __nv_bfloat16 hi = __float2bfloat16(v);
    __nv_bfloat16 lo = __float2bfloat16(v - __bfloat162float(hi));
    g_wth[n * C_ + k] = hi;
    g_wtl[n * C_ + k] = lo;
  }
}

// ---------------------------------------------------------------------------
// Kernel 1: QKV projection on tensor cores.
// out[16384 x 192] = x[16384 x 1024] @ WT^T, 3-term bf16 split mma.
// BM=64, BN=192 (full), BK=32. 8 warps = 2(M) x 4(N); warp tile 32 x 48.
// x split to bf16 hi/lo on the fly. q/k written row-major bf16x2 pairs;
// V transposed through smem for coalesced [b][h][t] stores.
// ---------------------------------------------------------------------------
#define GK_S 40                       // bf16 stride (80B rows, conflict-free)
#define A_OFF 0                        // Ah at 0, Al at 64*GK_S
#define B_OFF (2 * 64 * GK_S)          // Bh, then Bl
#define SM_TOT (2 * 64 * GK_S + 2 * 192 * GK_S)   // 20480 bf16 = 40960 B
#define VT_S 66                        // V transpose tile stride

__global__ __launch_bounds__(256, 2) void qkv_gemm(const float* __restrict__ x) {
  __shared__ __nv_bfloat16 smb[SM_TOT];
  __nv_bfloat16* Ah = smb;
  __nv_bfloat16* Al = smb + 64 * GK_S;
  __nv_bfloat16* Bh = smb + B_OFF;
  __nv_bfloat16* Bl = smb + B_OFF + 192 * GK_S;

  const int t = threadIdx.x;
  const int warp = t >> 5, lane = t & 31;
  const int g = lane >> 2, c = lane & 3;
  const int wm = warp >> 2;       // 0..1  (32 rows each)
  const int wn = warp & 3;        // 0..3  (48 cols each)
  const int row0 = blockIdx.x * 64;

  float acc[2][6][4];
#pragma unroll
  for (int mt = 0; mt < 2; mt++)
#pragma unroll
    for (int nt = 0; nt < 6; nt++)
#pragma unroll
      for (int r = 0; r < 4; r++) acc[mt][nt][r] = 0.f;

  const uint4* wthp = (const uint4*)g_wth;   // 128 uint4 per 1024-col row
  const uint4* wtlp = (const uint4*)g_wtl;

  // prefetch chunk 0
  float4 xr[2];
  uint4 bhr[3], blr[3];
#pragma unroll
  for (int i = 0; i < 2; i++) {
    int f = i * 256 + t, row = f >> 3, c4 = f & 7;
    xr[i] = *(const float4*)(x + (row0 + row) * C_ + c4 * 4);
  }
#pragma unroll
  for (int i = 0; i < 3; i++) {
    int f = i * 256 + t, n = f >> 2, seg = f & 3;
    bhr[i] = wthp[n * 128 + seg];
    blr[i] = wtlp[n * 128 + seg];
  }

  for (int kc = 0; kc < 32; kc++) {
    __syncthreads();   // prev chunk's smem reads complete
#pragma unroll
    for (int i = 0; i < 2; i++) {
      int f = i * 256 + t, row = f >> 3, c4 = f & 7;
      float4 v = xr[i];
      __nv_bfloat162 h0 = __floats2bfloat162_rn(v.x, v.y);
      __nv_bfloat162 h1 = __floats2bfloat162_rn(v.z, v.w);
      float2 f0 = __bfloat1622float2(h0);
      float2 f1 = __bfloat1622float2(h1);
      __nv_bfloat162 l0 = __floats2bfloat162_rn(v.x - f0.x, v.y - f0.y);
      __nv_bfloat162 l1 = __floats2bfloat162_rn(v.z - f1.x, v.w - f1.y);
      uint2 hu, lu;
      hu.x = *(unsigned*)&h0; hu.y = *(unsigned*)&h1;
      lu.x = *(unsigned*)&l0; lu.y = *(unsigned*)&l1;
      *(uint2*)&Ah[row * GK_S + c4 * 4] = hu;
      *(uint2*)&Al[row * GK_S + c4 * 4] = lu;
    }
#pragma unroll
    for (int i = 0; i < 3; i++) {
      int f = i * 256 + t, n = f >> 2, seg = f & 3;
      *(uint4*)&Bh[n * GK_S + seg * 8] = bhr[i];
      *(uint4*)&Bl[n * GK_S + seg * 8] = blr[i];
    }
    __syncthreads();   // tiles visible

    if (kc + 1 < 32) {
      int k0 = (kc + 1) * 32;
#pragma unroll
      for (int i = 0; i < 2; i++) {
        int f = i * 256 + t, row = f >> 3, c4 = f & 7;
        xr[i] = *(const float4*)(x + (row0 + row) * C_ + k0 + c4 * 4);
      }
#pragma unroll
      for (int i = 0; i < 3; i++) {
        int f = i * 256 + t, n = f >> 2, seg = f & 3;
        bhr[i] = wthp[n * 128 + (k0 >> 3) + seg];
        blr[i] = wtlp[n * 128 + (k0 >> 3) + seg];
      }
    }

#pragma unroll
    for (int ks = 0; ks < 2; ks++) {
      unsigned ah[2][4], al[2][4];
#pragma unroll
      for (int mt = 0; mt < 2; mt++) {
        int ra = (wm * 32 + mt * 16 + g) * GK_S + ks * 16 + 2 * c;
        int rb = ra + 8 * GK_S;
        ah[mt][0] = LDU(Ah[ra]);      ah[mt][1] = LDU(Ah[rb]);
        ah[mt][2] = LDU(Ah[ra + 8]);  ah[mt][3] = LDU(Ah[rb + 8]);
        al[mt][0] = LDU(Al[ra]);      al[mt][1] = LDU(Al[rb]);
        al[mt][2] = LDU(Al[ra + 8]);  al[mt][3] = LDU(Al[rb + 8]);
      }
#pragma unroll
      for (int nt = 0; nt < 6; nt++) {
        int nb = (wn * 48 + nt * 8 + g) * GK_S + ks * 16 + 2 * c;
        unsigned b0h = LDU(Bh[nb]), b1h = LDU(Bh[nb + 8]);
        unsigned b0l = LDU(Bl[nb]), b1l = LDU(Bl[nb + 8]);
#pragma unroll
        for (int mt = 0; mt < 2; mt++) {
          mma_bf16(acc[mt][nt], ah[mt], b0h, b1h);
          mma_bf16(acc[mt][nt], ah[mt], b0l, b1l);
          mma_bf16(acc[mt][nt], al[mt], b0h, b1h);
        }
      }
    }
  }

  // ---- writeback q/k: coalesced bf16x2 pairs ----
#pragma unroll
  for (int mt = 0; mt < 2; mt++) {
#pragma unroll
    for (int nt = 0; nt < 6; nt++) {
      int n0 = wn * 48 + nt * 8;
      int arr = n0 >> 6;
      if (arr < 2) {
        __nv_bfloat16* dh = arr ? g_kh : g_qh;
        __nv_bfloat16* dl = arr ? g_kl : g_ql;
        int hcol = (n0 & 63) + 2 * c;
        int r0 = row0 + wm * 32 + mt * 16 + g;
#pragma unroll
        for (int half = 0; half < 2; half++) {
          float d0 = acc[mt][nt][half * 2], d1 = acc[mt][nt][half * 2 + 1];
          int row = r0 + half * 8;
          __nv_bfloat162 hh = __floats2bfloat162_rn(d0, d1);
          float2 hf = __bfloat1622float2(hh);
          __nv_bfloat162 ll = __floats2bfloat162_rn(d0 - hf.x, d1 - hf.y);
          *(unsigned*)&dh[row * H_ + hcol] = *(unsigned*)&hh;
          *(unsigned*)&dl[row * H_ + hcol] = *(unsigned*)&ll;
        }
      }
    }
  }

  // ---- writeback V: stage [t][h] tile in smem, store coalesced [b][h][t] ----
  __syncthreads();   // all mma smem reads done; reuse smb
  __nv_bfloat16* Vth = smb;                    // 64 x 66
  __nv_bfloat16* Vtl = smb + 64 * VT_S;
#pragma unroll
  for (int mt = 0; mt < 2; mt++) {
#pragma unroll
    for (int nt = 0; nt < 6; nt++) {
      int n0 = wn * 48 + nt * 8;
      if ((n0 >> 6) == 2) {
        int h0 = (n0 - 128) + 2 * c;
        int rl0 = wm * 32 + mt * 16 + g;
#pragma unroll
        for (int half = 0; half < 2; half++) {
          float d0 = acc[mt][nt][half * 2], d1 = acc[mt][nt][half * 2 + 1];
          int rl = rl0 + half * 8;
          __nv_bfloat162 hh = __floats2bfloat162_rn(d0, d1);
          float2 hf = __bfloat1622float2(hh);
          __nv_bfloat162 ll = __floats2bfloat162_rn(d0 - hf.x, d1 - hf.y);
          *(unsigned*)&Vth[rl * VT_S + h0] = *(unsigned*)&hh;
          *(unsigned*)&Vtl[rl * VT_S + h0] = *(unsigned*)&ll;
        }
      }
    }
  }
  __syncthreads();

  {
    const int bb = row0 >> 11;            // batch
    const int tt0 = row0 & 2047;          // position base
    const int h = t >> 2, seg = t & 3;    // 64 h-rows x 4 segments of 16
    union { __nv_bfloat16 b[16]; uint4 u[2]; } th, tl;
#pragma unroll
    for (int i = 0; i < 16; i++) {
      th.b[i] = Vth[(seg * 16 + i) * VT_S + h];
      tl.b[i] = Vtl[(seg * 16 + i) * VT_S + h];
    }
    __nv_bfloat16* dsth = g_vth + (bb * H_ + h) * T_ + tt0 + seg * 16;
    __nv_bfloat16* dstl = g_vtl + (bb * H_ + h) * T_ + tt0 + seg * 16;
    ((uint4*)dsth)[0] = th.u[0];
    ((uint4*)dsth)[1] = th.u[1];
    ((uint4*)dstl)[0] = tl.u[0];
    ((uint4*)dstl)[1] = tl.u[1];
  }
}

// ---------------------------------------------------------------------------
// Kernel 2: causal flash attention on tensor cores (unchanged from R3).
// ---------------------------------------------------------------------------
#define SKS 72
#define TILE_ELEMS (64 * SKS)
#define ATT_SMEM_BYTES (6 * TILE_ELEMS * 2 + 256 * 4)   // 56320

__global__ __launch_bounds__(256, 2) void attn_kernel(float* __restrict__ out) {
  extern __shared__ __nv_bfloat16 smb[];
  __nv_bfloat16* Kh  = smb;
  __nv_bfloat16* Kl  = smb + TILE_ELEMS;
  __nv_bfloat16* VTh = smb + 2 * TILE_ELEMS;
  __nv_bfloat16* VTl = smb + 3 * TILE_ELEMS;
  __nv_bfloat16* Ph  = smb + 4 * TILE_ELEMS;
  __nv_bfloat16* Pl  = smb + 5 * TILE_ELEMS;
  float* redmax = (float*)(smb + 6 * TILE_ELEMS);
  float* redsum = redmax + 128;

  const int t = threadIdx.x;
  const int warp = t >> 5, lane = t & 31;
  const int g = lane >> 2, c = lane & 3;
  const int wm = warp >> 1, wn = warp & 1;
  const int bx = blockIdx.x;
  const int qt = 31 - (bx >> 3);
  const int b  = bx & 7;
  const int bT = b * T_;
  const int qbase = qt * 64;

  unsigned qfh[4][4], qfl[4][4];
  {
    const unsigned* qhp = (const unsigned*)g_qh;
    const unsigned* qlp = (const unsigned*)g_ql;
    int r0 = (bT + qbase + wm * 16 + g) * 32;
    int r8 = r0 + 8 * 32;
#pragma unroll
    for (int ks = 0; ks < 4; ks++) {
      int off = ks * 8 + c;
      qfh[ks][0] = qhp[r0 + off];
      qfh[ks][1] = qhp[r8 + off];
      qfh[ks][2] = qhp[r0 + off + 4];
      qfh[ks][3] = qhp[r8 + off + 4];
      qfl[ks][0] = qlp[r0 + off];
      qfl[ks][1] = qlp[r8 + off];
      qfl[ks][2] = qlp[r0 + off + 4];
      qfl[ks][3] = qlp[r8 + off + 4];
    }
  }

  float o[4][4];
#pragma unroll
  for (int j = 0; j < 4; j++)
#pragma unroll
    for (int r = 0; r < 4; r++) o[j][r] = 0.f;
  float m0 = -1e30f, m1 = -1e30f, l0 = 0.f, l1 = 0.f;

  const unsigned* khp  = (const unsigned*)g_kh;
  const unsigned* klp  = (const unsigned*)g_kl;
  const unsigned* vthp = (const unsigned*)g_vth;
  const unsigned* vtlp = (const unsigned*)g_vtl;

  unsigned pk[16], pv[16];
#pragma unroll
  for (int i = 0; i < 8; i++) {
    int r = i * 8 + warp;
    pk[i]     = khp[(bT + r) * 32 + lane];
    pk[i + 8] = klp[(bT + r) * 32 + lane];
    pv[i]     = vthp[(b * 64 + r) * 1024 + lane];
    pv[i + 8] = vtlp[(b * 64 + r) * 1024 + lane];
  }

  const int nkt = qt + 1;
  for (int kt = 0; kt < nkt; kt++) {
    __syncthreads();
#pragma unroll
    for (int i = 0; i < 8; i++) {
      int so = (i * 8 + warp) * SKS + lane * 2;
      *(unsigned*)&Kh[so]  = pk[i];
      *(unsigned*)&Kl[so]  = pk[i + 8];
      *(unsigned*)&VTh[so] = pv[i];
      *(unsigned*)&VTl[so] = pv[i + 8];
    }
    __syncthreads();

    if (kt + 1 < nkt) {
      int kb2 = (kt + 1) * 64;
#pragma unroll
      for (int i = 0; i < 8; i++) {
        int r = i * 8 + warp;
        pk[i]     = khp[(bT + kb2 + r) * 32 + lane];
        pk[i + 8] = klp[(bT + kb2 + r) * 32 + lane];
        pv[i]     = vthp[(b * 64 + r) * 1024 + (kt + 1) * 32 + lane];
        pv[i + 8] = vtlp[(b * 64 + r) * 1024 + (kt + 1) * 32 + lane];
      }
    }

    float s[4][4];
#pragma unroll
    for (int j = 0; j < 4; j++)
#pragma unroll
      for (int r = 0; r < 4; r++) s[j][r] = 0.f;

#pragma unroll
    for (int ks = 0; ks < 4; ks++) {
#pragma unroll
      for (int j = 0; j < 4; j++) {
        int nr = (wn * 32 + j * 8 + g) * SKS + ks * 16 + 2 * c;
        unsigned bh0 = LDU(Kh[nr]);
        unsigned bh1 = LDU(Kh[nr + 8]);
        unsigned bl0 = LDU(Kl[nr]);
        unsigned bl1 = LDU(Kl[nr + 8]);
        mma_bf16(s[j], qfh[ks], bh0, bh1);
        mma_bf16(s[j], qfh[ks], bl0, bl1);
        mma_bf16(s[j], qfl[ks], bh0, bh1);
      }
    }

    const int kbase = kt * 64;
    const int qi0 = qbase + wm * 16 + g;
    const int qi1 = qi0 + 8;
#pragma unroll
    for (int j = 0; j < 4; j++) {
      s[j][0] *= 0.125f; s[j][1] *= 0.125f;
      s[j][2] *= 0.125f; s[j][3] *= 0.125f;
      if (kt == qt) {
        int col0 = kbase + wn * 32 + j * 8 + 2 * c;
        if (col0     > qi0) s[j][0] = -1e30f;
        if (col0 + 1 > qi0) s[j][1] = -1e30f;
        if (col0     > qi1) s[j][2] = -1e30f;
        if (col0 + 1 > qi1) s[j][3] = -1e30f;
      }
    }

    float mx0 = -1e30f, mx1 = -1e30f;
#pragma unroll
    for (int j = 0; j < 4; j++) {
      mx0 = fmaxf(mx0, fmaxf(s[j][0], s[j][1]));
      mx1 = fmaxf(mx1, fmaxf(s[j][2], s[j][3]));
    }
    mx0 = fmaxf(mx0, __shfl_xor_sync(0xffffffffu, mx0, 1));
    mx0 = fmaxf(mx0, __shfl_xor_sync(0xffffffffu, mx0, 2));
    mx1 = fmaxf(mx1, __shfl_xor_sync(0xffffffffu, mx1, 1));
    mx1 = fmaxf(mx1, __shfl_xor_sync(0xffffffffu, mx1, 2));
    if (c == 0) {
      redmax[wn * 64 + wm * 16 + g]     = mx0;
      redmax[wn * 64 + wm * 16 + 8 + g] = mx1;
    }
    __syncthreads();
    float M0 = fmaxf(m0, fmaxf(mx0, redmax[(1 - wn) * 64 + wm * 16 + g]));
    float M1 = fmaxf(m1, fmaxf(mx1, redmax[(1 - wn) * 64 + wm * 16 + 8 + g]));
    float a0 = __expf(m0 - M0);
    float a1 = __expf(m1 - M1);
    m0 = M0; m1 = M1;

    float ps0 = 0.f, ps1 = 0.f;
#pragma unroll
    for (int j = 0; j < 4; j++) {
      float p00 = __expf(s[j][0] - M0);
      float p01 = __expf(s[j][1] - M0);
      float p10 = __expf(s[j][2] - M1);
      float p11 = __expf(s[j][3] - M1);
      ps0 += p00 + p01;
      ps1 += p10 + p11;
      int pr0 = (wm * 16 + g) * SKS + wn * 32 + j * 8 + 2 * c;
      int pr1 = pr0 + 8 * SKS;
      __nv_bfloat162 h2 = __floats2bfloat162_rn(p00, p01);
      float2 hf = __bfloat1622float2(h2);
      __nv_bfloat162 l2 = __floats2bfloat162_rn(p00 - hf.x, p01 - hf.y);
      *(unsigned*)&Ph[pr0] = *(unsigned*)&h2;
      *(unsigned*)&Pl[pr0] = *(unsigned*)&l2;
      __nv_bfloat162 h3 = __floats2bfloat162_rn(p10, p11);
      float2 hg = __bfloat1622float2(h3);
      __nv_bfloat162 l3 = __floats2bfloat162_rn(p10 - hg.x, p11 - hg.y);
      *(unsigned*)&Ph[pr1] = *(unsigned*)&h3;
      *(unsigned*)&Pl[pr1] = *(unsigned*)&l3;
    }
    ps0 += __shfl_xor_sync(0xffffffffu, ps0, 1);
    ps0 += __shfl_xor_sync(0xffffffffu, ps0, 2);
    ps1 += __shfl_xor_sync(0xffffffffu, ps1, 1);
    ps1 += __shfl_xor_sync(0xffffffffu, ps1, 2);
    if (c == 0) {
      redsum[wn * 64 + wm * 16 + g]     = ps0;
      redsum[wn * 64 + wm * 16 + 8 + g] = ps1;
    }
    __syncthreads();
    l0 = l0 * a0 + ps0 + redsum[(1 - wn) * 64 + wm * 16 + g];
    l1 = l1 * a1 + ps1 + redsum[(1 - wn) * 64 + wm * 16 + 8 + g];

#pragma unroll
    for (int j = 0; j < 4; j++) {
      o[j][0] *= a0; o[j][1] *= a0;
      o[j][2] *= a1; o[j][3] *= a1;
    }
#pragma unroll
    for (int ks = 0; ks < 4; ks++) {
      unsigned pah[4], pal[4];
      int ar = (wm * 16 + g) * SKS + ks * 16 + 2 * c;
      pah[0] = LDU(Ph[ar]);
      pah[1] = LDU(Ph[ar + 8 * SKS]);
      pah[2] = LDU(Ph[ar + 8]);
      pah[3] = LDU(Ph[ar + 8 * SKS + 8]);
      pal[0] = LDU(Pl[ar]);
      pal[1] = LDU(Pl[ar + 8 * SKS]);
      pal[2] = LDU(Pl[ar + 8]);
      pal[3] = LDU(Pl[ar + 8 * SKS + 8]);
#pragma unroll
      for (int j = 0; j < 4; j++) {
        int br = (wn * 32 + j * 8 + g) * SKS + ks * 16 + 2 * c;
        unsigned vh0 = LDU(VTh[br]);
        unsigned vh1 = LDU(VTh[br + 8]);
        unsigned vl0 = LDU(VTl[br]);
        unsigned vl1 = LDU(VTl[br + 8]);
        mma_bf16(o[j], pah, vh0, vh1);
        mma_bf16(o[j], pah, vl0, vl1);
        mma_bf16(o[j], pal, vh0, vh1);
      }
    }
  }

  float i0 = 1.0f / l0, i1 = 1.0f / l1;
  int ob0 = (bT + qbase + wm * 16 + g) * H_ + wn * 32;
  int ob1 = ob0 + 8 * H_;
#pragma unroll
  for (int j = 0; j < 4; j++) {
    float2 r0 = make_float2(o[j][0] * i0, o[j][1] * i0);
    float2 r1 = make_float2(o[j][2] * i1, o[j][3] * i1);
    *(float2*)&out[ob0 + j * 8 + 2 * c] = r0;
    *(float2*)&out[ob1 + j * 8 + 2 * c] = r1;
  }
}

// ---------------------------------------------------------------------------
extern "C" void kernel_launch(void* const* d_in, const int* in_sizes, int n_in,
                              void* d_out, int out_size) {
  const float* x  = (const float*)d_in[0];
  const float* Wq = (const float*)d_in[1];
  const float* Wk = (const float*)d_in[2];
  const float* Wv = (const float*)d_in[3];
  float* out = (float*)d_out;

  cudaFuncSetAttribute(attn_kernel,
                       cudaFuncAttributeMaxDynamicSharedMemorySize,
                       ATT_SMEM_BYTES);

  wsplit_kernel<<<192, 256>>>(Wq, Wk, Wv);                // tiny
  qkv_gemm<<<M_TOTAL / 64, 256>>>(x);                     // 256 blocks
  attn_kernel<<<B_ * 32, 256, ATT_SMEM_BYTES>>>(out);     // 256 blocks
}

// round 6
// speedup vs baseline: 4.3828x; 1.6830x over previous
#include <cuda_runtime.h>
#include <cuda_bf16.h>
#include <cstdint>

#define B_ 8
#define T_ 2048
#define C_ 1024
#define H_ 64
#define M_TOTAL (B_ * T_)   // 16384 rows

// bf16 hi/lo split scratch (allocation-free rule: __device__ globals)
__device__ __align__(16) __nv_bfloat16 g_qh[M_TOTAL * H_];
__device__ __align__(16) __nv_bfloat16 g_ql[M_TOTAL * H_];
__device__ __align__(16) __nv_bfloat16 g_kh[M_TOTAL * H_];
__device__ __align__(16) __nv_bfloat16 g_kl[M_TOTAL * H_];
// V stored transposed per batch: [b][h][t]
__device__ __align__(16) __nv_bfloat16 g_vth[B_ * H_ * T_];
__device__ __align__(16) __nv_bfloat16 g_vtl[B_ * H_ * T_];
// Fused weight, transposed + split: row n = {q0..63, k0..63, v0..63}, k-major
__device__ __align__(16) __nv_bfloat16 g_wth[192 * 1024];
__device__ __align__(16) __nv_bfloat16 g_wtl[192 * 1024];

// ---------------------------------------------------------------------------
// Base-PTX helpers (sm_80+ only; compute_103 virtual arch blocks tcgen05)
// ---------------------------------------------------------------------------
__device__ __forceinline__ uint32_t smem_u32(const void* p) {
  uint32_t a;
  asm("{ .reg .u64 t; cvta.to.shared.u64 t, %1; cvt.u32.u64 %0, t; }"
      : "=r"(a) : "l"(p));
  return a;
}

__device__ __forceinline__ void mma_bf16(float d[4], const unsigned a[4],
                                         unsigned b0, unsigned b1) {
  asm volatile(
      "mma.sync.aligned.m16n8k16.row.col.f32.bf16.bf16.f32 "
      "{%0,%1,%2,%3}, {%4,%5,%6,%7}, {%8,%9}, {%0,%1,%2,%3};\n"
      : "+f"(d[0]), "+f"(d[1]), "+f"(d[2]), "+f"(d[3])
      : "r"(a[0]), "r"(a[1]), "r"(a[2]), "r"(a[3]), "r"(b0), "r"(b1));
}

__device__ __forceinline__ void ldsm4(unsigned r[4], uint32_t addr) {
  asm volatile(
      "ldmatrix.sync.aligned.m8n8.x4.shared.b16 {%0,%1,%2,%3}, [%4];\n"
      : "=r"(r[0]), "=r"(r[1]), "=r"(r[2]), "=r"(r[3]) : "r"(addr));
}

#define CP_ASYNC16(dst, src) \
  asm volatile("cp.async.cg.shared.global [%0], [%1], 16;\n" \
               :: "r"(dst), "l"(src))
#define CP_COMMIT() asm volatile("cp.async.commit_group;\n" ::: "memory")
#define CP_WAIT0()  asm volatile("cp.async.wait_group 0;\n" ::: "memory")

#define LDU(p) (*(const unsigned*)&(p))

// ---------------------------------------------------------------------------
// Kernel 0: coalesced weight transpose + hi/lo split (48 blocks).
// ---------------------------------------------------------------------------
__global__ __launch_bounds__(256) void wsplit_kernel(
    const float* __restrict__ Wq, const float* __restrict__ Wk,
    const float* __restrict__ Wv) {
  __shared__ float tile[64][65];
  const int t = threadIdx.x;
  const int w = blockIdx.x >> 4;          // 0..2
  const int k0 = (blockIdx.x & 15) * 64;  // k tile
  const float* W = (w == 0) ? Wq : (w == 1 ? Wk : Wv);

#pragma unroll
  for (int i = 0; i < 16; i++) {
    int idx = i * 256 + t;
    int r = idx >> 6, c = idx & 63;
    tile[r][c] = W[(size_t)(k0 + r) * H_ + c];
  }
  __syncthreads();

  const int h = t >> 2, seg = t & 3;
  union { __nv_bfloat16 b[16]; uint4 u[2]; } th, tl;
#pragma unroll
  for (int kk = 0; kk < 16; kk++) {
    float v = tile[seg * 16 + kk][h];
    __nv_bfloat16 hi = __float2bfloat16(v);
    th.b[kk] = hi;
    tl.b[kk] = __float2bfloat16(v - __bfloat162float(hi));
  }
  size_t base = (size_t)(w * 64 + h) * C_ + k0 + seg * 16;
  ((uint4*)(g_wth + base))[0] = th.u[0];
  ((uint4*)(g_wth + base))[1] = th.u[1];
  ((uint4*)(g_wtl + base))[0] = tl.u[0];
  ((uint4*)(g_wtl + base))[1] = tl.u[1];
}

// ---------------------------------------------------------------------------
// Kernel 1: QKV GEMM on legacy tensor cores, done right.
// out[16384 x 192] = x @ W^T, 3-term bf16 split (hi*hi + hi*lo + lo*hi).
// BM=128, BN=192, BK=32; 8 warps = 4(M) x 2(N), warp tile 32x96.
// ldmatrix.x4 fragment loads from stride-40 bf16 smem (conflict-free).
// Double-buffered: B via cp.async, A via register prefetch + convert.
// ---------------------------------------------------------------------------
#define A_STRIDE_B 80            // bytes per A/B smem row (40 bf16)
#define OFF_AH 0
#define OFF_AL 10240             // 128*80
#define OFF_BH 20480
#define OFF_BL 35840             // +192*80
#define ST_BYTES 51200
#define QKV_SMEM (2 * ST_BYTES)  // 102400
#define VTS 66                   // V transpose tile stride (bf16 elems)

__global__ __launch_bounds__(256, 1) void qkv_mma(const float* __restrict__ x) {
  extern __shared__ char sm[];
  const uint32_t sb = smem_u32(sm);
  const int t = threadIdx.x;
  const int lane = t & 31, warp = t >> 5;
  const int g = lane >> 2, c = lane & 3;
  const int lm = lane >> 3, lr = lane & 7;
  const int wm = warp >> 1, wn = warp & 1;   // 4(M) x 2(N)
  const int row0 = blockIdx.x * 128;

  float acc[2][12][4];
#pragma unroll
  for (int mt = 0; mt < 2; mt++)
#pragma unroll
    for (int nt = 0; nt < 12; nt++)
#pragma unroll
      for (int r = 0; r < 4; r++) acc[mt][nt][r] = 0.f;

  // ---- staging maps ----
  const int arow = t >> 1, ahalf = t & 1;   // A: thread = (row, 16-float half)
  const float* xptr = x + (size_t)(row0 + arow) * C_ + ahalf * 16;

  // ldmatrix lane-address components (bytes)
  // A frags: matrices (rows0-7,k0)(rows8-15,k0)(rows0-7,k8)(rows8-15,k8)
  uint32_t aoff[2][2], boff[6][2];
#pragma unroll
  for (int mt = 0; mt < 2; mt++)
#pragma unroll
    for (int ks = 0; ks < 2; ks++)
      aoff[mt][ks] = (uint32_t)((wm * 32 + mt * 16 + (lm & 1) * 8 + lr) * A_STRIDE_B +
                                (ks * 16 + (lm >> 1) * 8) * 2);
  // B frags: matrices (n0-7,k0)(n0-7,k8)(n8-15,k0)(n8-15,k8)
#pragma unroll
  for (int pair = 0; pair < 6; pair++)
#pragma unroll
    for (int ks = 0; ks < 2; ks++)
      boff[pair][ks] = (uint32_t)((wn * 96 + pair * 16 + (lm >> 1) * 8 + lr) * A_STRIDE_B +
                                  (ks * 16 + (lm & 1) * 8) * 2);

  // ---- helpers as lambdas ----
  auto storeA = [&](uint32_t base, const float4 xr[4]) {
    union { __nv_bfloat16 b[16]; uint4 u[2]; } hu, lu;
#pragma unroll
    for (int v4 = 0; v4 < 4; v4++) {
      const float* f = (const float*)&xr[v4];
#pragma unroll
      for (int e = 0; e < 4; e++) {
        __nv_bfloat16 hi = __float2bfloat16(f[e]);
        hu.b[v4 * 4 + e] = hi;
        lu.b[v4 * 4 + e] = __float2bfloat16(f[e] - __bfloat162float(hi));
      }
    }
    char* dst_h = sm + (base - sb) + OFF_AH + arow * A_STRIDE_B + ahalf * 32;
    char* dst_l = sm + (base - sb) + OFF_AL + arow * A_STRIDE_B + ahalf * 32;
    ((uint4*)dst_h)[0] = hu.u[0];
    ((uint4*)dst_h)[1] = hu.u[1];
    ((uint4*)dst_l)[0] = lu.u[0];
    ((uint4*)dst_l)[1] = lu.u[1];
  };

  auto issueB = [&](int kc, uint32_t base) {
#pragma unroll
    for (int i = 0; i < 3; i++) {
      int f = i * 256 + t;
      int row = f >> 2, seg = f & 3;
      uint32_t dh = base + OFF_BH + row * A_STRIDE_B + seg * 16;
      uint32_t dl = base + OFF_BL + row * A_STRIDE_B + seg * 16;
      const __nv_bfloat16* sh = g_wth + (size_t)row * C_ + kc * 32 + seg * 8;
      const __nv_bfloat16* sl = g_wtl + (size_t)row * C_ + kc * 32 + seg * 8;
      CP_ASYNC16(dh, sh);
      CP_ASYNC16(dl, sl);
    }
  };

  // ---- prologue: stage chunk 0, prefetch chunk 1 regs ----
  float4 xr[4];
#pragma unroll
  for (int i = 0; i < 4; i++) xr[i] = *(const float4*)(xptr + i * 4);
  storeA(sb, xr);
  issueB(0, sb);
  CP_COMMIT();
#pragma unroll
  for (int i = 0; i < 4; i++) xr[i] = *(const float4*)(xptr + 32 + i * 4);

  for (int kc = 0; kc < 32; kc++) {
    const uint32_t sbase = sb + (kc & 1) * ST_BYTES;
    const uint32_t nbase = sb + ((kc & 1) ^ 1) * ST_BYTES;

    CP_WAIT0();
    __syncthreads();   // stage(kc) fully staged; stage(kc+1) free of readers

    if (kc + 1 < 32) {
      issueB(kc + 1, nbase);
      CP_COMMIT();
    }

    // ---- compute chunk kc ----
#pragma unroll
    for (int ks = 0; ks < 2; ks++) {
      unsigned ah[2][4], al[2][4];
#pragma unroll
      for (int mt = 0; mt < 2; mt++) {
        ldsm4(ah[mt], sbase + OFF_AH + aoff[mt][ks]);
        ldsm4(al[mt], sbase + OFF_AL + aoff[mt][ks]);
      }
#pragma unroll
      for (int pair = 0; pair < 6; pair++) {
        unsigned bh[4], bl[4];
        ldsm4(bh, sbase + OFF_BH + boff[pair][ks]);
        ldsm4(bl, sbase + OFF_BL + boff[pair][ks]);
#pragma unroll
        for (int sub = 0; sub < 2; sub++) {
          const int nt = pair * 2 + sub;
          unsigned b0h = bh[sub * 2], b1h = bh[sub * 2 + 1];
          unsigned b0l = bl[sub * 2], b1l = bl[sub * 2 + 1];
#pragma unroll
          for (int mt = 0; mt < 2; mt++) {
            mma_bf16(acc[mt][nt], ah[mt], b0h, b1h);
            mma_bf16(acc[mt][nt], ah[mt], b0l, b1l);
            mma_bf16(acc[mt][nt], al[mt], b0h, b1h);
          }
        }
      }
    }

    if (kc + 1 < 32) {
      storeA(nbase, xr);
      if (kc + 2 < 32) {
#pragma unroll
        for (int i = 0; i < 4; i++)
          xr[i] = *(const float4*)(xptr + (kc + 2) * 32 + i * 4);
      }
    }
  }

  // ---- epilogue: q/k direct stores ----
#pragma unroll
  for (int mt = 0; mt < 2; mt++) {
#pragma unroll
    for (int nt = 0; nt < 12; nt++) {
      const int n0 = wn * 96 + nt * 8;
      const int arr = n0 >> 6;
      if (arr < 2) {
        __nv_bfloat16* dh = arr ? g_kh : g_qh;
        __nv_bfloat16* dl = arr ? g_kl : g_ql;
        const int hcol = (n0 & 63) + 2 * c;
#pragma unroll
        for (int half = 0; half < 2; half++) {
          float d0 = acc[mt][nt][half * 2], d1 = acc[mt][nt][half * 2 + 1];
          int row = row0 + wm * 32 + mt * 16 + g + half * 8;
          __nv_bfloat162 h2 = __floats2bfloat162_rn(d0, d1);
          float2 hf = __bfloat1622float2(h2);
          __nv_bfloat162 l2 = __floats2bfloat162_rn(d0 - hf.x, d1 - hf.y);
          *(unsigned*)&dh[(size_t)row * H_ + hcol] = *(unsigned*)&h2;
          *(unsigned*)&dl[(size_t)row * H_ + hcol] = *(unsigned*)&l2;
        }
      }
    }
  }

  // ---- epilogue: V via smem transpose (reuse stage memory) ----
  __syncthreads();   // all mma smem reads done
  __nv_bfloat16* Vsh = (__nv_bfloat16*)sm;
  __nv_bfloat16* Vsl = (__nv_bfloat16*)(sm + 128 * VTS * 2);
  if (wn == 1) {
#pragma unroll
    for (int mt = 0; mt < 2; mt++) {
#pragma unroll
      for (int nt = 4; nt < 12; nt++) {
        const int n0 = 96 + nt * 8;            // 128..184
        const int vcol = (n0 - 128) + 2 * c;
#pragma unroll
        for (int half = 0; half < 2; half++) {
          float d0 = acc[mt][nt][half * 2], d1 = acc[mt][nt][half * 2 + 1];
          int rl = wm * 32 + mt * 16 + g + half * 8;
          __nv_bfloat162 h2 = __floats2bfloat162_rn(d0, d1);
          float2 hf = __bfloat1622float2(h2);
          __nv_bfloat162 l2 = __floats2bfloat162_rn(d0 - hf.x, d1 - hf.y);
          *(unsigned*)&Vsh[rl * VTS + vcol] = *(unsigned*)&h2;
          *(unsigned*)&Vsl[rl * VTS + vcol] = *(unsigned*)&l2;
        }
      }
    }
  }
  __syncthreads();
  {
    const int h = t & 63, q = t >> 6;
    const int bb = row0 >> 11;
    const int tt0 = row0 & 2047;
    union { __nv_bfloat16 b[32]; uint4 u[4]; } th, tl;
#pragma unroll
    for (int i = 0; i < 32; i++) {
      th.b[i] = Vsh[(q * 32 + i) * VTS + h];
      tl.b[i] = Vsl[(q * 32 + i) * VTS + h];
    }
    __nv_bfloat16* dh = g_vth + (size_t)(bb * H_ + h) * T_ + tt0 + q * 32;
    __nv_bfloat16* dl = g_vtl + (size_t)(bb * H_ + h) * T_ + tt0 + q * 32;
#pragma unroll
    for (int u = 0; u < 4; u++) {
      ((uint4*)dh)[u] = th.u[u];
      ((uint4*)dl)[u] = tl.u[u];
    }
  }
}

// ---------------------------------------------------------------------------
// Kernel 2: causal flash attention on tensor cores (unchanged, known-good 92us)
// ---------------------------------------------------------------------------
#define SKS 72
#define TILE_ELEMS (64 * SKS)
#define ATT_SMEM_BYTES (6 * TILE_ELEMS * 2 + 256 * 4)   // 56320

__global__ __launch_bounds__(256, 2) void attn_kernel(float* __restrict__ out) {
  extern __shared__ __nv_bfloat16 smb[];
  __nv_bfloat16* Kh  = smb;
  __nv_bfloat16* Kl  = smb + TILE_ELEMS;
  __nv_bfloat16* VTh = smb + 2 * TILE_ELEMS;
  __nv_bfloat16* VTl = smb + 3 * TILE_ELEMS;
  __nv_bfloat16* Ph  = smb + 4 * TILE_ELEMS;
  __nv_bfloat16* Pl  = smb + 5 * TILE_ELEMS;
  float* redmax = (float*)(smb + 6 * TILE_ELEMS);
  float* redsum = redmax + 128;

  const int t = threadIdx.x;
  const int warp = t >> 5, lane = t & 31;
  const int g = lane >> 2, c = lane & 3;
  const int wm = warp >> 1, wn = warp & 1;
  const int bx = blockIdx.x;
  const int qt = 31 - (bx >> 3);
  const int b  = bx & 7;
  const int bT = b * T_;
  const int qbase = qt * 64;

  unsigned qfh[4][4], qfl[4][4];
  {
    const unsigned* qhp = (const unsigned*)g_qh;
    const unsigned* qlp = (const unsigned*)g_ql;
    int r0 = (bT + qbase + wm * 16 + g) * 32;
    int r8 = r0 + 8 * 32;
#pragma unroll
    for (int ks = 0; ks < 4; ks++) {
      int off = ks * 8 + c;
      qfh[ks][0] = qhp[r0 + off];
      qfh[ks][1] = qhp[r8 + off];
      qfh[ks][2] = qhp[r0 + off + 4];
      qfh[ks][3] = qhp[r8 + off + 4];
      qfl[ks][0] = qlp[r0 + off];
      qfl[ks][1] = qlp[r8 + off];
      qfl[ks][2] = qlp[r0 + off + 4];
      qfl[ks][3] = qlp[r8 + off + 4];
    }
  }

  float o[4][4];
#pragma unroll
  for (int j = 0; j < 4; j++)
#pragma unroll
    for (int r = 0; r < 4; r++) o[j][r] = 0.f;
  float m0 = -1e30f, m1 = -1e30f, l0 = 0.f, l1 = 0.f;

  const unsigned* khp  = (const unsigned*)g_kh;
  const unsigned* klp  = (const unsigned*)g_kl;
  const unsigned* vthp = (const unsigned*)g_vth;
  const unsigned* vtlp = (const unsigned*)g_vtl;

  unsigned pk[16], pv[16];
#pragma unroll
  for (int i = 0; i < 8; i++) {
    int r = i * 8 + warp;
    pk[i]     = khp[(bT + r) * 32 + lane];
    pk[i + 8] = klp[(bT + r) * 32 + lane];
    pv[i]     = vthp[(b * 64 + r) * 1024 + lane];
    pv[i + 8] = vtlp[(b * 64 + r) * 1024 + lane];
  }

  const int nkt = qt + 1;
  for (int kt = 0; kt < nkt; kt++) {
    __syncthreads();
#pragma unroll
    for (int i = 0; i < 8; i++) {
      int so = (i * 8 + warp) * SKS + lane * 2;
      *(unsigned*)&Kh[so]  = pk[i];
      *(unsigned*)&Kl[so]  = pk[i + 8];
      *(unsigned*)&VTh[so] = pv[i];
      *(unsigned*)&VTl[so] = pv[i + 8];
    }
    __syncthreads();

    if (kt + 1 < nkt) {
      int kb2 = (kt + 1) * 64;
#pragma unroll
      for (int i = 0; i < 8; i++) {
        int r = i * 8 + warp;
        pk[i]     = khp[(bT + kb2 + r) * 32 + lane];
        pk[i + 8] = klp[(bT + kb2 + r) * 32 + lane];
        pv[i]     = vthp[(b * 64 + r) * 1024 + (kt + 1) * 32 + lane];
        pv[i + 8] = vtlp[(b * 64 + r) * 1024 + (kt + 1) * 32 + lane];
      }
    }

    float s[4][4];
#pragma unroll
    for (int j = 0; j < 4; j++)
#pragma unroll
      for (int r = 0; r < 4; r++) s[j][r] = 0.f;

#pragma unroll
    for (int ks = 0; ks < 4; ks++) {
#pragma unroll
      for (int j = 0; j < 4; j++) {
        int nr = (wn * 32 + j * 8 + g) * SKS + ks * 16 + 2 * c;
        unsigned bh0 = LDU(Kh[nr]);
        unsigned bh1 = LDU(Kh[nr + 8]);
        unsigned bl0 = LDU(Kl[nr]);
        unsigned bl1 = LDU(Kl[nr + 8]);
        mma_bf16(s[j], qfh[ks], bh0, bh1);
        mma_bf16(s[j], qfh[ks], bl0, bl1);
        mma_bf16(s[j], qfl[ks], bh0, bh1);
      }
    }

    const int kbase = kt * 64;
    const int qi0 = qbase + wm * 16 + g;
    const int qi1 = qi0 + 8;
#pragma unroll
    for (int j = 0; j < 4; j++) {
      s[j][0] *= 0.125f; s[j][1] *= 0.125f;
      s[j][2] *= 0.125f; s[j][3] *= 0.125f;
      if (kt == qt) {
        int col0 = kbase + wn * 32 + j * 8 + 2 * c;
        if (col0     > qi0) s[j][0] = -1e30f;
        if (col0 + 1 > qi0) s[j][1] = -1e30f;
        if (col0     > qi1) s[j][2] = -1e30f;
        if (col0 + 1 > qi1) s[j][3] = -1e30f;
      }
    }

    float mx0 = -1e30f, mx1 = -1e30f;
#pragma unroll
    for (int j = 0; j < 4; j++) {
      mx0 = fmaxf(mx0, fmaxf(s[j][0], s[j][1]));
      mx1 = fmaxf(mx1, fmaxf(s[j][2], s[j][3]));
    }
    mx0 = fmaxf(mx0, __shfl_xor_sync(0xffffffffu, mx0, 1));
    mx0 = fmaxf(mx0, __shfl_xor_sync(0xffffffffu, mx0, 2));
    mx1 = fmaxf(mx1, __shfl_xor_sync(0xffffffffu, mx1, 1));
    mx1 = fmaxf(mx1, __shfl_xor_sync(0xffffffffu, mx1, 2));
    if (c == 0) {
      redmax[wn * 64 + wm * 16 + g]     = mx0;
      redmax[wn * 64 + wm * 16 + 8 + g] = mx1;
    }
    __syncthreads();
    float M0 = fmaxf(m0, fmaxf(mx0, redmax[(1 - wn) * 64 + wm * 16 + g]));
    float M1 = fmaxf(m1, fmaxf(mx1, redmax[(1 - wn) * 64 + wm * 16 + 8 + g]));
    float a0 = __expf(m0 - M0);
    float a1 = __expf(m1 - M1);
    m0 = M0; m1 = M1;

    float ps0 = 0.f, ps1 = 0.f;
#pragma unroll
    for (int j = 0; j < 4; j++) {
      float p00 = __expf(s[j][0] - M0);
      float p01 = __expf(s[j][1] - M0);
      float p10 = __expf(s[j][2] - M1);
      float p11 = __expf(s[j][3] - M1);
      ps0 += p00 + p01;
      ps1 += p10 + p11;
      int pr0 = (wm * 16 + g) * SKS + wn * 32 + j * 8 + 2 * c;
      int pr1 = pr0 + 8 * SKS;
      __nv_bfloat162 h2 = __floats2bfloat162_rn(p00, p01);
      float2 hf = __bfloat1622float2(h2);
      __nv_bfloat162 l2 = __floats2bfloat162_rn(p00 - hf.x, p01 - hf.y);
      *(unsigned*)&Ph[pr0] = *(unsigned*)&h2;
      *(unsigned*)&Pl[pr0] = *(unsigned*)&l2;
      __nv_bfloat162 h3 = __floats2bfloat162_rn(p10, p11);
      float2 hg = __bfloat1622float2(h3);
      __nv_bfloat162 l3 = __floats2bfloat162_rn(p10 - hg.x, p11 - hg.y);
      *(unsigned*)&Ph[pr1] = *(unsigned*)&h3;
      *(unsigned*)&Pl[pr1] = *(unsigned*)&l3;
    }
    ps0 += __shfl_xor_sync(0xffffffffu, ps0, 1);
    ps0 += __shfl_xor_sync(0xffffffffu, ps0, 2);
    ps1 += __shfl_xor_sync(0xffffffffu, ps1, 1);
    ps1 += __shfl_xor_sync(0xffffffffu, ps1, 2);
    if (c == 0) {
      redsum[wn * 64 + wm * 16 + g]     = ps0;
      redsum[wn * 64 + wm * 16 + 8 + g] = ps1;
    }
    __syncthreads();
    l0 = l0 * a0 + ps0 + redsum[(1 - wn) * 64 + wm * 16 + g];
    l1 = l1 * a1 + ps1 + redsum[(1 - wn) * 64 + wm * 16 + 8 + g];

#pragma unroll
    for (int j = 0; j < 4; j++) {
      o[j][0] *= a0; o[j][1] *= a0;
      o[j][2] *= a1; o[j][3] *= a1;
    }
#pragma unroll
    for (int ks = 0; ks < 4; ks++) {
      unsigned pah[4], pal[4];
      int ar = (wm * 16 + g) * SKS + ks * 16 + 2 * c;
      pah[0] = LDU(Ph[ar]);
      pah[1] = LDU(Ph[ar + 8 * SKS]);
      pah[2] = LDU(Ph[ar + 8]);
      pah[3] = LDU(Ph[ar + 8 * SKS + 8]);
      pal[0] = LDU(Pl[ar]);
      pal[1] = LDU(Pl[ar + 8 * SKS]);
      pal[2] = LDU(Pl[ar + 8]);
      pal[3] = LDU(Pl[ar + 8 * SKS + 8]);
#pragma unroll
      for (int j = 0; j < 4; j++) {
        int br = (wn * 32 + j * 8 + g) * SKS + ks * 16 + 2 * c;
        unsigned vh0 = LDU(VTh[br]);
        unsigned vh1 = LDU(VTh[br + 8]);
        unsigned vl0 = LDU(VTl[br]);
        unsigned vl1 = LDU(VTl[br + 8]);
        mma_bf16(o[j], pah, vh0, vh1);
        mma_bf16(o[j], pah, vl0, vl1);
        mma_bf16(o[j], pal, vh0, vh1);
      }
    }
  }

  float i0 = 1.0f / l0, i1 = 1.0f / l1;
  int ob0 = (bT + qbase + wm * 16 + g) * H_ + wn * 32;
  int ob1 = ob0 + 8 * H_;
#pragma unroll
  for (int j = 0; j < 4; j++) {
    float2 r0 = make_float2(o[j][0] * i0, o[j][1] * i0);
    float2 r1 = make_float2(o[j][2] * i1, o[j][3] * i1);
    *(float2*)&out[ob0 + j * 8 + 2 * c] = r0;
    *(float2*)&out[ob1 + j * 8 + 2 * c] = r1;
  }
}

// ---------------------------------------------------------------------------
extern "C" void kernel_launch(void* const* d_in, const int* in_sizes, int n_in,
                              void* d_out, int out_size) {
  const float* x  = (const float*)d_in[0];
  const float* Wq = (const float*)d_in[1];
  const float* Wk = (const float*)d_in[2];
  const float* Wv = (const float*)d_in[3];
  float* out = (float*)d_out;

  cudaFuncSetAttribute(qkv_mma,
                       cudaFuncAttributeMaxDynamicSharedMemorySize, QKV_SMEM);
  cudaFuncSetAttribute(attn_kernel,
                       cudaFuncAttributeMaxDynamicSharedMemorySize,
                       ATT_SMEM_BYTES);

  wsplit_kernel<<<48, 256>>>(Wq, Wk, Wv);                   // ~2 us
  qkv_mma<<<M_TOTAL / 128, 256, QKV_SMEM>>>(x);             // 128 blocks
  attn_kernel<<<B_ * 32, 256, ATT_SMEM_BYTES>>>(out);       // 256 blocks
}